// round 4
// baseline (speedup 1.0000x reference)
#include <cuda_runtime.h>
#include <cstdint>

// Sufficient statistics: M4[n][a][b][c][d] = sum_t A[t,n,a,b] * B[t,n,c,d]
__device__ float g_M4[17 * 81];

#define NJ 17
#define ROWSTRIDE (NJ * 9)   // 153 floats per t

// ---------------------------------------------------------------------------
// Kernel 1: reduction over t (double accumulation for accuracy)
// grid = (17, 9): block (n, ab) computes M4[n][ab][0..8]
// ---------------------------------------------------------------------------
__global__ __launch_bounds__(256) void reduce_kernel(
    const float* __restrict__ A, const float* __restrict__ B, int T)
{
    const int n  = blockIdx.x;
    const int ab = blockIdx.y;
    const float* An = A + n * 9 + ab;
    const float* Bn = B + n * 9;

    double acc[9];
#pragma unroll
    for (int cd = 0; cd < 9; cd++) acc[cd] = 0.0;

    for (int t = threadIdx.x; t < T; t += 256) {
        const size_t off = (size_t)t * ROWSTRIDE;
        double a = (double)An[off];
        const float* Br = Bn + off;
#pragma unroll
        for (int cd = 0; cd < 9; cd++)
            acc[cd] = fma(a, (double)Br[cd], acc[cd]);
    }

    // warp reduce
    const unsigned lane = threadIdx.x & 31u;
    const unsigned w    = threadIdx.x >> 5;
#pragma unroll
    for (int off = 16; off > 0; off >>= 1) {
#pragma unroll
        for (int cd = 0; cd < 9; cd++)
            acc[cd] += __shfl_down_sync(0xFFFFFFFFu, acc[cd], off);
    }

    __shared__ double sred[8][9];
    if (lane == 0) {
#pragma unroll
        for (int cd = 0; cd < 9; cd++) sred[w][cd] = acc[cd];
    }
    __syncthreads();

    if (threadIdx.x < 9) {
        double s = 0.0;
#pragma unroll
        for (int ww = 0; ww < 8; ww++) s += sred[ww][threadIdx.x];
        g_M4[(n * 9 + ab) * 9 + threadIdx.x] = (float)s;
    }
}

// ---------------------------------------------------------------------------
// Threefry-2x32-20 (exact JAX PRNG), key = jax.random.key(1) -> (0, 1)
// ---------------------------------------------------------------------------
__device__ __forceinline__ unsigned rotl32(unsigned x, int d) {
    return (x << d) | (x >> (32 - d));
}
__device__ __forceinline__ void tf_round4(unsigned& x0, unsigned& x1,
                                          int a, int b, int c, int d) {
    x0 += x1; x1 = rotl32(x1, a); x1 ^= x0;
    x0 += x1; x1 = rotl32(x1, b); x1 ^= x0;
    x0 += x1; x1 = rotl32(x1, c); x1 ^= x0;
    x0 += x1; x1 = rotl32(x1, d); x1 ^= x0;
}
__device__ __forceinline__ void threefry2x32_01(unsigned x0, unsigned x1,
                                                unsigned& o0, unsigned& o1) {
    const unsigned ks0 = 0u, ks1 = 1u, ks2 = 0x1BD11BDAu ^ 0u ^ 1u;
    x0 += ks0; x1 += ks1;
    tf_round4(x0, x1, 13, 15, 26, 6);  x0 += ks1; x1 += ks2 + 1u;
    tf_round4(x0, x1, 17, 29, 16, 24); x0 += ks2; x1 += ks0 + 2u;
    tf_round4(x0, x1, 13, 15, 26, 6);  x0 += ks0; x1 += ks1 + 3u;
    tf_round4(x0, x1, 17, 29, 16, 24); x0 += ks1; x1 += ks2 + 4u;
    tf_round4(x0, x1, 13, 15, 26, 6);  x0 += ks2; x1 += ks0 + 5u;
    o0 = x0; o1 = x1;
}

// ---------------------------------------------------------------------------
// Kernel 2: single-warp Adam solver. Lane n owns joint n; W[n] (9x9 operator,
// -2*lw folded) lives in registers; 450 iterations fully on-chip.
// ---------------------------------------------------------------------------
__global__ __launch_bounds__(32) void solve_kernel(float* __restrict__ out)
{
    const int lane = threadIdx.x;
    const int n = (lane < NJ) ? lane : 0;
    const float* M = g_M4 + n * 81;

    // W[(p,q)][(j,k)] = -2*lw * ( M4[p,j,q,k] + M4[j,p,k,q] ),  lw = 10
    float W[81];
#pragma unroll
    for (int p = 0; p < 3; p++)
#pragma unroll
    for (int q = 0; q < 3; q++)
#pragma unroll
    for (int j = 0; j < 3; j++)
#pragma unroll
    for (int k = 0; k < 3; k++) {
        float l1 = M[((p * 3 + j) * 3 + q) * 3 + k];
        float l2 = M[((j * 3 + p) * 3 + k) * 3 + q];
        W[(p * 3 + q) * 9 + (j * 3 + k)] = -20.0f * (l1 + l2);
    }

    // ang0 = jax.random.uniform(key(1), (17,3), f32) with
    // jax_threefry_partitionable=True:
    //   flat element i: (o0,o1) = threefry2x32(key=(0,1), x=(hi(i)=0, lo(i)=i))
    //   32-bit stream  = o0 ^ o1   (XOR-fold of the 64-bit block)
    //   f = bitcast((bits32 >> 9) | 0x3F800000) - 1
    float ang[3];
#pragma unroll
    for (int j = 0; j < 3; j++) {
        int i = n * 3 + j;
        unsigned o0, o1;
        threefry2x32_01(0u, (unsigned)i, o0, o1);
        unsigned bits = o0 ^ o1;
        ang[j] = __uint_as_float((bits >> 9) | 0x3F800000u) - 1.0f;
    }

    float m[3] = {0.f, 0.f, 0.f}, v[3] = {0.f, 0.f, 0.f};
    float b1p = 1.0f, b2p = 1.0f;

    for (int it = 0; it < 450; it++) {
        const float lr = (it < 150) ? 0.01f : ((it < 300) ? 0.009f : 0.0081f);

        // Rodrigues
        float t2 = ang[0] * ang[0] + ang[1] * ang[1] + ang[2] * ang[2];
        float th = sqrtf(t2);
        float ts = fmaxf(th, 1e-12f);
        float inv = 1.0f / ts;
        float k0 = ang[0] * inv, k1 = ang[1] * inv, k2 = ang[2] * inv;
        float c = cosf(th), s = sinf(th);
        float omc = 1.0f - c;

        float C[9];
        C[0] = fmaf(omc * k0, k0,  c);
        C[1] = fmaf(omc * k0, k1, -s * k2);
        C[2] = fmaf(omc * k0, k2,  s * k1);
        C[3] = fmaf(omc * k1, k0,  s * k2);
        C[4] = fmaf(omc * k1, k1,  c);
        C[5] = fmaf(omc * k1, k2, -s * k0);
        C[6] = fmaf(omc * k2, k0, -s * k1);
        C[7] = fmaf(omc * k2, k1,  s * k0);
        C[8] = fmaf(omc * k2, k2,  c);

        // Ambient gradient G = W * vec(C)   (9x9 * 9)
        float G[9];
#pragma unroll
        for (int p = 0; p < 9; p++) {
            float acc = W[p * 9] * C[0];
#pragma unroll
            for (int q = 1; q < 9; q++) acc = fmaf(W[p * 9 + q], C[q], acc);
            G[p] = acc;
        }

        // Rodrigues VJP: g_m = <G, dC/dr_m>
        float trG = G[0] + G[4] + G[8];
        float a0 = G[5] - G[7], a1 = G[6] - G[2], a2 = G[1] - G[3];
        float kda = k0 * a0 + k1 * a1 + k2 * a2;
        float u0 = G[0] * k0 + G[1] * k1 + G[2] * k2;   // G k
        float u1 = G[3] * k0 + G[4] * k1 + G[5] * k2;
        float u2 = G[6] * k0 + G[7] * k1 + G[8] * k2;
        float w0 = G[0] * k0 + G[3] * k1 + G[6] * k2;   // G^T k
        float w1 = G[1] * k0 + G[4] * k1 + G[7] * k2;
        float w2 = G[2] * k0 + G[5] * k1 + G[8] * k2;
        float kGk = k0 * u0 + k1 * u1 + k2 * u2;

        float coef = s * kGk - s * trG - c * kda;
        float so = s * inv, co = omc * inv;
        float g0 = k0 * coef + so * (kda * k0 - a0) + co * (u0 + w0 - 2.0f * kGk * k0);
        float g1 = k1 * coef + so * (kda * k1 - a1) + co * (u1 + w1 - 2.0f * kGk * k1);
        float g2 = k2 * coef + so * (kda * k2 - a2) + co * (u2 + w2 - 2.0f * kGk * k2);
        float g[3] = {g0, g1, g2};

        // Adam
        b1p *= 0.9f; b2p *= 0.999f;
        float rb1 = 1.0f / (1.0f - b1p);
        float rb2 = 1.0f / (1.0f - b2p);
#pragma unroll
        for (int j = 0; j < 3; j++) {
            m[j] = fmaf(0.9f,   m[j], 0.1f   * g[j]);
            v[j] = fmaf(0.999f, v[j], 0.001f * g[j] * g[j]);
            float mh = m[j] * rb1;
            float vh = v[j] * rb2;
            ang[j] = ang[j] - lr * mh / (sqrtf(vh) + 1e-8f);
        }
    }

    if (lane < NJ) {
        out[n * 3 + 0] = ang[0];
        out[n * 3 + 1] = ang[1];
        out[n * 3 + 2] = ang[2];
    }
}

// ---------------------------------------------------------------------------
extern "C" void kernel_launch(void* const* d_in, const int* in_sizes, int n_in,
                              void* d_out, int out_size)
{
    const float* A = (const float*)d_in[0];   // orgGyros (T,17,3,3)
    const float* B = (const float*)d_in[1];   // trgGyros (T,17,3,3)
    const int T = in_sizes[0] / ROWSTRIDE;

    dim3 grid(NJ, 9);
    reduce_kernel<<<grid, 256>>>(A, B, T);
    solve_kernel<<<1, 32>>>((float*)d_out);
}

// round 5
// speedup vs baseline: 2.8701x; 2.8701x over previous
#include <cuda_runtime.h>
#include <cstdint>

#define NJ 17
#define ROWSTRIDE 153          // 17*9 floats per timestep
#define NB 256                 // reduce blocks
#define SUB 32                 // staged timesteps per smem tile
#define NPART 1377             // 17*81 = 153*9 partial sums per block

__device__ float  g_part[NB * NPART];
__device__ float  g_M4[NPART]; // M4[n][ab][cd] flat

// ---------------------------------------------------------------------------
// Kernel 1: coalesced one-pass reduction.
// Block b handles timesteps [b*tchunk, b*tchunk+tchunk). Stages SUB full rows
// of A and B into smem (contiguous float4 copy), then 153 threads (n,ab)
// accumulate acc[cd] += A[t,n,ab] * B[t,n,cd] in f32.
// ---------------------------------------------------------------------------
__global__ __launch_bounds__(256) void reduce2(
    const float* __restrict__ A, const float* __restrict__ B,
    int T, int tchunk)
{
    __shared__ float As[SUB * ROWSTRIDE];
    __shared__ float Bs[SUB * ROWSTRIDE];

    const int tid   = threadIdx.x;
    const int t0    = blockIdx.x * tchunk;
    const int i     = tid;               // (n,ab) for i < 153
    const int nbase = (i / 9) * 9;       // n*9

    float acc[9] = {0.f,0.f,0.f,0.f,0.f,0.f,0.f,0.f,0.f};

    for (int s = 0; s < tchunk; s += SUB) {
        const int tb   = t0 + s;
        const int rows = (T - tb < SUB) ? (T - tb) : SUB;
        if (rows <= 0) break;

        const float* Ag = A + (size_t)tb * ROWSTRIDE;
        const float* Bg = B + (size_t)tb * ROWSTRIDE;

        if (rows == SUB) {
            // SUB*ROWSTRIDE = 4896 floats = 1224 float4 (16B aligned: tb%32==0)
            const float4* Ag4 = (const float4*)Ag;
            const float4* Bg4 = (const float4*)Bg;
            float4* As4 = (float4*)As;
            float4* Bs4 = (float4*)Bs;
#pragma unroll 3
            for (int j = tid; j < SUB * ROWSTRIDE / 4; j += 256) {
                As4[j] = Ag4[j];
                Bs4[j] = Bg4[j];
            }
        } else {
            for (int j = tid; j < rows * ROWSTRIDE; j += 256) {
                As[j] = Ag[j];
                Bs[j] = Bg[j];
            }
        }
        __syncthreads();

        if (i < NJ * 9) {
            for (int t = 0; t < rows; t++) {
                const float a  = As[t * ROWSTRIDE + i];
                const float* b = &Bs[t * ROWSTRIDE + nbase];
#pragma unroll
                for (int cd = 0; cd < 9; cd++)
                    acc[cd] = fmaf(a, b[cd], acc[cd]);
            }
        }
        __syncthreads();
    }

    if (i < NJ * 9) {
        float* p = g_part + (size_t)blockIdx.x * NPART + i * 9;
#pragma unroll
        for (int cd = 0; cd < 9; cd++) p[cd] = acc[cd];
    }
}

// ---------------------------------------------------------------------------
// Kernel 1b: deterministic double-precision combine of the NB partials.
// ---------------------------------------------------------------------------
__global__ void finalize_kernel(int nb)
{
    const int idx = blockIdx.x * blockDim.x + threadIdx.x;
    if (idx >= NPART) return;
    double s = 0.0;
    for (int b = 0; b < nb; b++)
        s += (double)g_part[b * NPART + idx];
    g_M4[idx] = (float)s;
}

// ---------------------------------------------------------------------------
// Threefry-2x32-20 (exact JAX PRNG), key = jax.random.key(1) -> (0, 1)
// ---------------------------------------------------------------------------
__device__ __forceinline__ unsigned rotl32(unsigned x, int d) {
    return (x << d) | (x >> (32 - d));
}
__device__ __forceinline__ void tf_round4(unsigned& x0, unsigned& x1,
                                          int a, int b, int c, int d) {
    x0 += x1; x1 = rotl32(x1, a); x1 ^= x0;
    x0 += x1; x1 = rotl32(x1, b); x1 ^= x0;
    x0 += x1; x1 = rotl32(x1, c); x1 ^= x0;
    x0 += x1; x1 = rotl32(x1, d); x1 ^= x0;
}
__device__ __forceinline__ void threefry2x32_01(unsigned x0, unsigned x1,
                                                unsigned& o0, unsigned& o1) {
    const unsigned ks0 = 0u, ks1 = 1u, ks2 = 0x1BD11BDAu ^ 0u ^ 1u;
    x0 += ks0; x1 += ks1;
    tf_round4(x0, x1, 13, 15, 26, 6);  x0 += ks1; x1 += ks2 + 1u;
    tf_round4(x0, x1, 17, 29, 16, 24); x0 += ks2; x1 += ks0 + 2u;
    tf_round4(x0, x1, 13, 15, 26, 6);  x0 += ks0; x1 += ks1 + 3u;
    tf_round4(x0, x1, 17, 29, 16, 24); x0 += ks1; x1 += ks2 + 4u;
    tf_round4(x0, x1, 13, 15, 26, 6);  x0 += ks2; x1 += ks0 + 5u;
    o0 = x0; o1 = x1;
}

// ---------------------------------------------------------------------------
// Kernel 2: single-warp Adam solver with fast intrinsics. Lane n owns joint n;
// W[n] (9x9, -2*lw folded) lives in registers; 450 iterations on-chip.
// ---------------------------------------------------------------------------
__global__ __launch_bounds__(32) void solve_kernel(float* __restrict__ out)
{
    const int lane = threadIdx.x;
    const int n = (lane < NJ) ? lane : 0;
    const float* M = g_M4 + n * 81;

    // W[(p,q)][(j,k)] = -2*lw * ( M4[p,j,q,k] + M4[j,p,k,q] ),  lw = 10
    float W[81];
#pragma unroll
    for (int p = 0; p < 3; p++)
#pragma unroll
    for (int q = 0; q < 3; q++)
#pragma unroll
    for (int j = 0; j < 3; j++)
#pragma unroll
    for (int k = 0; k < 3; k++) {
        float l1 = M[((p * 3 + j) * 3 + q) * 3 + k];
        float l2 = M[((j * 3 + p) * 3 + k) * 3 + q];
        W[(p * 3 + q) * 9 + (j * 3 + k)] = -20.0f * (l1 + l2);
    }

    // ang0 = uniform(key(1),(17,3)) with partitionable threefry:
    // bits32(i) = o0 ^ o1 of threefry2x32((0,1), (0, i))
    float ang[3];
#pragma unroll
    for (int j = 0; j < 3; j++) {
        int i = n * 3 + j;
        unsigned o0, o1;
        threefry2x32_01(0u, (unsigned)i, o0, o1);
        unsigned bits = o0 ^ o1;
        ang[j] = __uint_as_float((bits >> 9) | 0x3F800000u) - 1.0f;
    }

    float m[3] = {0.f, 0.f, 0.f}, v[3] = {0.f, 0.f, 0.f};
    float b1p = 1.0f, b2p = 1.0f;

    for (int it = 0; it < 450; it++) {
        const float lr = (it < 150) ? 0.01f : ((it < 300) ? 0.009f : 0.0081f);

        // Rodrigues (rsqrt-based; t2=0 edge handled by clamp)
        float t2 = ang[0] * ang[0] + ang[1] * ang[1] + ang[2] * ang[2];
        float inv = rsqrtf(fmaxf(t2, 1e-24f));   // 1/theta
        float th = t2 * inv;                     // theta
        float k0 = ang[0] * inv, k1 = ang[1] * inv, k2 = ang[2] * inv;
        float c = __cosf(th), s = __sinf(th);
        float omc = 1.0f - c;

        float C[9];
        C[0] = fmaf(omc * k0, k0,  c);
        C[1] = fmaf(omc * k0, k1, -s * k2);
        C[2] = fmaf(omc * k0, k2,  s * k1);
        C[3] = fmaf(omc * k1, k0,  s * k2);
        C[4] = fmaf(omc * k1, k1,  c);
        C[5] = fmaf(omc * k1, k2, -s * k0);
        C[6] = fmaf(omc * k2, k0, -s * k1);
        C[7] = fmaf(omc * k2, k1,  s * k0);
        C[8] = fmaf(omc * k2, k2,  c);

        // Ambient gradient G = W * vec(C)
        float G[9];
#pragma unroll
        for (int p = 0; p < 9; p++) {
            float acc = W[p * 9] * C[0];
#pragma unroll
            for (int q = 1; q < 9; q++) acc = fmaf(W[p * 9 + q], C[q], acc);
            G[p] = acc;
        }

        // Rodrigues VJP: g_m = <G, dC/dr_m>
        float trG = G[0] + G[4] + G[8];
        float a0 = G[5] - G[7], a1 = G[6] - G[2], a2 = G[1] - G[3];
        float kda = k0 * a0 + k1 * a1 + k2 * a2;
        float u0 = G[0] * k0 + G[1] * k1 + G[2] * k2;   // G k
        float u1 = G[3] * k0 + G[4] * k1 + G[5] * k2;
        float u2 = G[6] * k0 + G[7] * k1 + G[8] * k2;
        float w0 = G[0] * k0 + G[3] * k1 + G[6] * k2;   // G^T k
        float w1 = G[1] * k0 + G[4] * k1 + G[7] * k2;
        float w2 = G[2] * k0 + G[5] * k1 + G[8] * k2;
        float kGk = k0 * u0 + k1 * u1 + k2 * u2;

        float coef = s * kGk - s * trG - c * kda;
        float so = s * inv, co = omc * inv;
        float g0 = k0 * coef + so * (kda * k0 - a0) + co * (u0 + w0 - 2.0f * kGk * k0);
        float g1 = k1 * coef + so * (kda * k1 - a1) + co * (u1 + w1 - 2.0f * kGk * k1);
        float g2 = k2 * coef + so * (kda * k2 - a2) + co * (u2 + w2 - 2.0f * kGk * k2);
        float g[3] = {g0, g1, g2};

        // Adam (fast reciprocals / sqrt-via-rsqrt, exact-zero safe)
        b1p *= 0.9f; b2p *= 0.999f;
        float rb1 = __fdividef(1.0f, 1.0f - b1p);
        float rb2 = __fdividef(1.0f, 1.0f - b2p);
#pragma unroll
        for (int j = 0; j < 3; j++) {
            m[j] = fmaf(0.9f,   m[j], 0.1f   * g[j]);
            v[j] = fmaf(0.999f, v[j], 0.001f * g[j] * g[j]);
            float mh = m[j] * rb1;
            float vh = v[j] * rb2;
            float sq = vh * rsqrtf(fmaxf(vh, 1e-38f));   // sqrt(vh), 0-safe
            ang[j] = ang[j] - __fdividef(lr * mh, sq + 1e-8f);
        }
    }

    if (lane < NJ) {
        out[n * 3 + 0] = ang[0];
        out[n * 3 + 1] = ang[1];
        out[n * 3 + 2] = ang[2];
    }
}

// ---------------------------------------------------------------------------
extern "C" void kernel_launch(void* const* d_in, const int* in_sizes, int n_in,
                              void* d_out, int out_size)
{
    const float* A = (const float*)d_in[0];   // orgGyros (T,17,3,3)
    const float* B = (const float*)d_in[1];   // trgGyros (T,17,3,3)
    const int T = in_sizes[0] / ROWSTRIDE;

    // round tchunk up to a multiple of SUB
    int tchunk = (T + NB - 1) / NB;
    tchunk = (tchunk + SUB - 1) / SUB * SUB;

    reduce2<<<NB, 256>>>(A, B, T, tchunk);
    finalize_kernel<<<(NPART + 255) / 256, 256>>>(NB);
    solve_kernel<<<1, 32>>>((float*)d_out);
}